// round 7
// baseline (speedup 1.0000x reference)
#include <cuda_runtime.h>
#include <math.h>

// ---------------------------------------------------------------------------
// YoloV1Loss — R7: ONE persistent kernel.
//  - 148 blocks (1/SM), 256 threads; block-stride over 256-row tiles.
//  - cp.async.cg double-buffered staging (tile k+1 in flight while computing
//    tile k) -> DRAM never idles within a block (fixes the 42%-DRAM phase
//    oscillation seen R3-R6).
//  - last persistent block finalizes (148 fences total, meta L2-hot), killing
//    the 11.4us K2 launch floor.
// ---------------------------------------------------------------------------

#define TPB   256
#define RPT   256
#define MAXT  4096
#define NCLS  20
#define BUFF  (RPT * 30)            // 7680 floats per array per buffer

__device__ float4   g_meta[MAXT];            // (csum, noobj, count, 0)
__device__ float    g_contrib[MAXT * RPT];   // rank-compacted per tile
__device__ unsigned g_done;                  // zero-init; finalizer resets

__global__ void __launch_bounds__(TPB, 1)
yolo_persist(const float* __restrict__ p, const float* __restrict__ t,
             float* __restrict__ out, int nrows, int nt) {
    extern __shared__ float smem[];          // 2 bufs x (7680 p + 7680 t)
    __shared__ int    wtot[TPB / 32];
    __shared__ float  wredN[TPB / 32];
    __shared__ float  wredC[TPB / 32];
    __shared__ double sd[TPB / 32];
    __shared__ int    s_bb, s_take;
    __shared__ unsigned s_rank;

    const int tid    = threadIdx.x;
    const int lane   = tid & 31;
    const int wid    = tid >> 5;
    const int stride = gridDim.x;
    const int n_my   = (nt > (int)blockIdx.x)
                     ? ((nt - (int)blockIdx.x + stride - 1) / stride) : 0;

    // ---- stage tile into buffer via cp.async (one commit group/thread) ----
    auto stage = [&](int tile, int buf) {
        const size_t base = (size_t)tile * RPT * 30;
        const int rows = min(RPT, nrows - tile * RPT);
        const int n16  = (rows * 30) >> 2;            // 16B units
        const float* pg = p + base;
        const float* tg = t + base;
        float* bp = smem + buf * (2 * BUFF);
        float* bt = bp + BUFF;
        const unsigned ap = (unsigned)__cvta_generic_to_shared(bp);
        const unsigned at = (unsigned)__cvta_generic_to_shared(bt);
        for (int i = tid; i < n16; i += TPB) {
            asm volatile("cp.async.cg.shared.global [%0], [%1], 16;\n"
                         :: "r"(ap + i * 16), "l"(pg + i * 4));
            asm volatile("cp.async.cg.shared.global [%0], [%1], 16;\n"
                         :: "r"(at + i * 16), "l"(tg + i * 4));
        }
        for (int i = (n16 << 2) + tid; i < rows * 30; i += TPB) {  // odd tail
            bp[i] = pg[i];
            bt[i] = tg[i];
        }
        asm volatile("cp.async.commit_group;\n" ::: "memory");
    };

    // ---- per-tile compute (row per thread, from smem) ----
    auto compute = [&](int tile, int buf) {
        const int row0 = tile * RPT;
        const int rows = min(RPT, nrows - row0);
        const float* bp = smem + buf * (2 * BUFF);
        const float* bt = bp + BUFF;
        const bool inrange = (tid < rows);
        const float* pr = bp + tid * 30;
        const float* tr = bt + tid * 30;

        const float conf = inrange ? tr[4] : -1.0f;
        const bool  cm   = (conf == 1.0f);

        const unsigned bal = __ballot_sync(0xffffffffu, cm);
        unsigned le_mask;
        asm("mov.u32 %0, %%lanemask_le;" : "=r"(le_mask));
        const int inc = __popc(bal & le_mask);
        if (lane == 31) wtot[wid] = __popc(bal);
        __syncthreads();
        int woff = 0, ctot = 0;
#pragma unroll
        for (int i = 0; i < TPB / 32; i++) {
            const int c = wtot[i];
            if (i < wid) woff += c;
            ctot += c;
        }

        float nv = 0.0f;
        if (inrange && conf == 0.0f) {
            const float d0 = pr[4] - tr[4];
            const float d1 = pr[9] - tr[9];
            nv = 0.5f * (d0 * d0 + d1 * d1);
        }

        float cv = 0.0f;
        if (cm) {
            const float C = 1.0f / 7.0f;
            const float tb0 = tr[0] * tr[0], tb1 = tr[1] * tr[1];
            const float tb2 = tr[2] * tr[2], tb3 = tr[3] * tr[3];
            const float tax = tb0 * C - tb2, tay = tb1 * C - tb3;
            const float tbx = tax * C + tb2, tby = tay * C + tb3;
            const float at2 = (tbx - tax) * (tby - tay);

            float iou0 = 0.0f, iou1 = 0.0f;
#pragma unroll
            for (int b = 0; b < 2; b++) {
                const float x = pr[b * 5 + 0], y = pr[b * 5 + 1];
                const float w = pr[b * 5 + 2], h = pr[b * 5 + 3];
                const float ax = x * C - w,  ay = y * C - h;
                const float bx = ax * C + w, by = ay * C + h;
                const float iw = fmaxf(fminf(bx, tbx) - fmaxf(ax, tax), 0.0f);
                const float ih = fmaxf(fminf(by, tby) - fmaxf(ay, tay), 0.0f);
                const float inter = iw * ih;
                const float ap2 = (bx - ax) * (by - ay);
                const float iou = inter / (ap2 + at2 - inter);
                if (b == 0) iou0 = iou; else iou1 = iou;
            }
            int idx;
            if (isnan(iou0))      idx = 0;  // numpy argmax: NaN wins, first.
            else if (isnan(iou1)) idx = 1;
            else                  idx = (iou1 > iou0) ? 1 : 0;

            const int ob = idx * 5;
            const float s0 = pr[ob + 0] - tr[0];
            const float s1 = pr[ob + 1] - tr[1];
            const float s2 = pr[ob + 2] - tr[2];
            const float s3 = pr[ob + 3] - tr[3];

            float best = tr[10];
            float clp  = pr[10];
#pragma unroll
            for (int j = 1; j < NCLS; j++) {
                const float v = tr[10 + j];
                const bool  u = (v > best);
                best = u ? v : best;
                clp  = u ? pr[10 + j] : clp;
            }
            const float clv = clp - 1.0f;

            cv = 5.0f * (s0 * s0 + s1 * s1 + s2 * s2 + s3 * s3 +
                         2.0f * clv * clv);
            g_contrib[tile * RPT + (woff + inc - 1)] = cv;
        }

        float nvr = nv, cvr = cv;
#pragma unroll
        for (int o = 16; o > 0; o >>= 1) {
            nvr += __shfl_down_sync(0xffffffffu, nvr, o);
            cvr += __shfl_down_sync(0xffffffffu, cvr, o);
        }
        if (lane == 0) { wredN[wid] = nvr; wredC[wid] = cvr; }
        __syncthreads();
        if (tid == 0) {
            float sn = 0.0f, sc = 0.0f;
#pragma unroll
            for (int i = 0; i < TPB / 32; i++) { sn += wredN[i]; sc += wredC[i]; }
            g_meta[tile] = make_float4(sc, sn, __int_as_float(ctot), 0.0f);
        }
    };

    // ---- double-buffered pipeline over my tiles ----
    if (n_my > 0) stage((int)blockIdx.x, 0);
    if (n_my > 1) stage((int)blockIdx.x + stride, 1);
    for (int k = 0; k < n_my; k++) {
        if (n_my - k > 1)
            asm volatile("cp.async.wait_group 1;\n" ::: "memory");
        else
            asm volatile("cp.async.wait_group 0;\n" ::: "memory");
        __syncthreads();
        const int tile = (int)blockIdx.x + k * stride;
        compute(tile, k & 1);
        __syncthreads();                       // buffer free + shared reuse
        if (k + 2 < n_my) stage((int)blockIdx.x + (k + 2) * stride, k & 1);
    }

    // =================== last-block finalize ===================
    __threadfence();                            // release my meta/contrib
    if (tid == 0) s_rank = atomicAdd(&g_done, 1u);
    __syncthreads();
    if (s_rank != (unsigned)(gridDim.x - 1)) return;
    __threadfence();                            // acquire others' writes

    const int CH = (nt + TPB - 1) / TPB;
    const int i0 = tid * CH;

    if (tid == 0) { s_bb = -1; s_take = 0; }

    // pass 1: per-thread chunk count sum (meta is L2-hot)
    int lsum = 0;
    for (int k = 0; k < CH; k++) {
        const int i = i0 + k;
        if (i < nt) lsum += __float_as_int(g_meta[i].z);
    }
    int incs = lsum;
#pragma unroll
    for (int o = 1; o < 32; o <<= 1) {
        const int x = __shfl_up_sync(0xffffffffu, incs, o);
        if (lane >= o) incs += x;
    }
    const int ex = incs - lsum;
    if (lane == 31) wtot[wid] = incs;
    __syncthreads();
    int wbase = 0, total = 0;
#pragma unroll
    for (int i = 0; i < TPB / 32; i++) {
        const int c = wtot[i];
        if (i < wid) wbase += c;
        total += c;
    }
    const int half = total >> 1;                // n_obj // 2

    // pass 2: gated sum; locate the single boundary tile
    double acc = 0.0;
    int P = wbase + ex;
    for (int k = 0; k < CH; k++) {
        const int i = i0 + k;
        if (i < nt) {
            const float4 m   = g_meta[i];
            const int    cnt = __float_as_int(m.z);
            const int   take = min(cnt, max(0, half - P));
            if (take == cnt)    acc += (double)m.x;
            else if (take > 0) { s_bb = i; s_take = take; }
            acc += (double)m.y;
            P += cnt;
        }
    }
    __syncthreads();

    if (s_bb >= 0) {                            // <=256-float partial
        const float* cb = g_contrib + s_bb * RPT;
        for (int i = tid; i < s_take; i += TPB) acc += (double)cb[i];
    }

#pragma unroll
    for (int o = 16; o > 0; o >>= 1)
        acc += __shfl_down_sync(0xffffffffu, acc, o);
    if (lane == 0) sd[wid] = acc;
    __syncthreads();
    if (tid == 0) {
        double s = 0.0;
#pragma unroll
        for (int i = 0; i < TPB / 32; i++) s += sd[i];
        out[0] = (float)s;
        g_done = 0u;                            // reset for next replay
    }
}

// ---------------------------------------------------------------------------
extern "C" void kernel_launch(void* const* d_in, const int* in_sizes, int n_in,
                              void* d_out, int out_size) {
    const float* p = (const float*)d_in[0];
    const float* t = (const float*)d_in[1];

    const int nrows = in_sizes[0] / 30;
    const int nt    = (nrows + RPT - 1) / RPT;

    const int smem_bytes = 2 * 2 * BUFF * (int)sizeof(float);   // 122880
    cudaFuncSetAttribute(yolo_persist,
                         cudaFuncAttributeMaxDynamicSharedMemorySize,
                         smem_bytes);

    const int grid = (nt < 148) ? nt : 148;
    yolo_persist<<<grid, TPB, smem_bytes>>>(p, t, (float*)d_out, nrows, nt);
}